// round 4
// baseline (speedup 1.0000x reference)
#include <cuda_runtime.h>
#include <cuda_bf16.h>

#define C32 32
#define D8  8

typedef unsigned long long ull;

// Precomputed folded matrices (device scratch; no allocation).
__device__ __align__(16) float g_M1T[D8 * C32];   // M1T[d][i] = sum_j A[i][j] * W1[j][d]
__device__ __align__(16) float g_c1[C32];         // c1[i] = sum_j A[i][j] * b1[j]
__device__ __align__(16) float g_M2T[C32 * C32];  // M2T[k][i] = sum_j A[i][j] * W2[j][k]
__device__ __align__(16) float g_c2[C32];         // c2[i] = sum_j A[i][j] * b2[j]

// ---- packed f32x2 helpers (Blackwell FFMA2; PTX-only pattern) ----
__device__ __forceinline__ ull pk2(float lo, float hi) {
    ull r;
    asm("mov.b64 %0, {%1, %2};" : "=l"(r) : "f"(lo), "f"(hi));
    return r;
}
__device__ __forceinline__ void upk2(ull v, float& lo, float& hi) {
    asm("mov.b64 {%0, %1}, %2;" : "=f"(lo), "=f"(hi) : "l"(v));
}
__device__ __forceinline__ void fma2(ull& d, ull a, ull b) {
#if __CUDA_ARCH__ >= 1000
    asm("fma.rn.f32x2 %0, %1, %2, %0;" : "+l"(d) : "l"(a), "l"(b));
#else
    float dl, dh, al, ah, bl, bh;
    upk2(d, dl, dh); upk2(a, al, ah); upk2(b, bl, bh);
    d = pk2(fmaf(al, bl, dl), fmaf(ah, bh, dh));
#endif
}

// ============================================================================
// Precompute: normalized adjacency folded into both linear layers.
// One block of 1024 threads; runs once per graph replay (cheap).
// ============================================================================
__global__ void gnn_precompute_kernel(const float* __restrict__ adjacency,
                                      const float* __restrict__ W1,
                                      const float* __restrict__ b1,
                                      const float* __restrict__ W2,
                                      const float* __restrict__ b2) {
    __shared__ float A[C32][C32];
    __shared__ float dis[C32];
    int t = threadIdx.x;
    int i = t >> 5;
    int j = t & 31;

    // adj = adjacency + I
    float a = adjacency[i * C32 + j] + (i == j ? 1.0f : 0.0f);
    A[i][j] = a;
    __syncthreads();

    if (j == 0) {
        float s = 0.0f;
        #pragma unroll
        for (int k = 0; k < C32; k++) s += A[i][k];
        dis[i] = rsqrtf(s + 1e-6f);
    }
    __syncthreads();

    float na = dis[i] * A[i][j] * dis[j];
    __syncthreads();
    A[i][j] = na;   // A is now norm_adj
    __syncthreads();

    // M2T[k][i] = sum_j A[i][j] * W2[j][k]   (thread (i, k=j))
    {
        int k = j;
        float s = 0.0f;
        #pragma unroll
        for (int jj = 0; jj < C32; jj++) s += A[i][jj] * W2[jj * C32 + k];
        g_M2T[k * C32 + i] = s;
    }
    // M1T[d][i] = sum_j A[i][j] * W1[j][d]   (threads 0..255)
    if (t < C32 * D8) {
        int ii = t >> 3;
        int d  = t & 7;
        float s = 0.0f;
        #pragma unroll
        for (int jj = 0; jj < C32; jj++) s += A[ii][jj] * W1[jj * D8 + d];
        g_M1T[d * C32 + ii] = s;
    }
    // c1, c2
    if (t < C32) {
        float s1 = 0.0f, s2 = 0.0f;
        #pragma unroll
        for (int jj = 0; jj < C32; jj++) {
            s1 += A[t][jj] * b1[jj];
            s2 += A[t][jj] * b2[jj];
        }
        g_c1[t] = s1;
        g_c2[t] = s2;
    }
}

// ============================================================================
// Main fused kernel: one (bt,c) row per thread.
//   h1 = relu(x@M1 + c1); h1 = LN(h1)*g1+be1
//   h2 = relu(h1@M2 + c2); out = LN(h2)*g2+be2
// All matmuls on packed f32x2 FMA; constants broadcast from shared.
// ============================================================================
__global__ __launch_bounds__(256) void gnn_main_kernel(
    const float* __restrict__ x,
    const float* __restrict__ g1, const float* __restrict__ be1,
    const float* __restrict__ g2, const float* __restrict__ be2,
    float* __restrict__ out, int nrows) {

    __shared__ __align__(16) float sM1T[D8 * C32];
    __shared__ __align__(16) float sc1[C32];
    __shared__ __align__(16) float sM2T[C32 * C32];
    __shared__ __align__(16) float sc2[C32];
    __shared__ float sg1[C32], sbe1[C32], sg2[C32], sbe2[C32];

    int t = threadIdx.x;
    for (int idx = t; idx < D8 * C32; idx += 256) sM1T[idx] = g_M1T[idx];
    for (int idx = t; idx < C32 * C32; idx += 256) sM2T[idx] = g_M2T[idx];
    if (t < C32) {
        sc1[t] = g_c1[t]; sc2[t] = g_c2[t];
        sg1[t] = g1[t];   sbe1[t] = be1[t];
        sg2[t] = g2[t];   sbe2[t] = be2[t];
    }
    __syncthreads();

    int row = blockIdx.x * 256 + t;
    if (row >= nrows) return;

    // Load x row (8 floats)
    const float4* xv = reinterpret_cast<const float4*>(x + (size_t)row * D8);
    float4 xa = xv[0];
    float4 xb = xv[1];
    float xr[8] = {xa.x, xa.y, xa.z, xa.w, xb.x, xb.y, xb.z, xb.w};

    // ---- Layer 1 matmul: h1[i] = c1[i] + sum_d xr[d]*M1T[d][i] ----
    ull h1p[16];
    #pragma unroll
    for (int i = 0; i < 16; i++)
        h1p[i] = *reinterpret_cast<const ull*>(&sc1[2 * i]);
    #pragma unroll
    for (int d = 0; d < D8; d++) {
        ull ad = pk2(xr[d], xr[d]);
        #pragma unroll
        for (int i = 0; i < 16; i++)
            fma2(h1p[i], ad, *reinterpret_cast<const ull*>(&sM1T[d * C32 + 2 * i]));
    }

    // ---- relu + LN1 ----
    float v[C32];
    float s = 0.0f, ss = 0.0f;
    #pragma unroll
    for (int i = 0; i < 16; i++) {
        float lo, hi;
        upk2(h1p[i], lo, hi);
        lo = fmaxf(lo, 0.0f);
        hi = fmaxf(hi, 0.0f);
        v[2 * i] = lo; v[2 * i + 1] = hi;
        s += lo + hi;
        ss += lo * lo + hi * hi;
    }
    float m = s * (1.0f / 32.0f);
    float var = ss * (1.0f / 32.0f) - m * m;
    float r = rsqrtf(var + 1e-5f);
    #pragma unroll
    for (int k = 0; k < C32; k++)
        v[k] = (v[k] - m) * r * sg1[k] + sbe1[k];

    // ---- Layer 2 matmul: h2[i] = c2[i] + sum_k v[k]*M2T[k][i] ----
    ull h2p[16];
    #pragma unroll
    for (int i = 0; i < 16; i++)
        h2p[i] = *reinterpret_cast<const ull*>(&sc2[2 * i]);
    #pragma unroll
    for (int k = 0; k < C32; k++) {
        ull ak = pk2(v[k], v[k]);
        #pragma unroll
        for (int i = 0; i < 16; i++)
            fma2(h2p[i], ak, *reinterpret_cast<const ull*>(&sM2T[k * C32 + 2 * i]));
    }

    // ---- relu + LN2 (pass 1: stats) ----
    float s2 = 0.0f, ss2 = 0.0f;
    #pragma unroll
    for (int i = 0; i < 16; i++) {
        float lo, hi;
        upk2(h2p[i], lo, hi);
        lo = fmaxf(lo, 0.0f);
        hi = fmaxf(hi, 0.0f);
        s2 += lo + hi;
        ss2 += lo * lo + hi * hi;
    }
    float m2 = s2 * (1.0f / 32.0f);
    float var2 = ss2 * (1.0f / 32.0f) - m2 * m2;
    float r2 = rsqrtf(var2 + 1e-5f);

    // ---- pass 2: affine + vectorized store (128 B per thread) ----
    float* op = out + (size_t)row * C32;
    #pragma unroll
    for (int q = 0; q < 8; q++) {
        float a0, a1, a2, a3;
        upk2(h2p[2 * q],     a0, a1);
        upk2(h2p[2 * q + 1], a2, a3);
        a0 = fmaxf(a0, 0.0f); a1 = fmaxf(a1, 0.0f);
        a2 = fmaxf(a2, 0.0f); a3 = fmaxf(a3, 0.0f);
        float4 o;
        o.x = (a0 - m2) * r2 * sg2[4 * q + 0] + sbe2[4 * q + 0];
        o.y = (a1 - m2) * r2 * sg2[4 * q + 1] + sbe2[4 * q + 1];
        o.z = (a2 - m2) * r2 * sg2[4 * q + 2] + sbe2[4 * q + 2];
        o.w = (a3 - m2) * r2 * sg2[4 * q + 3] + sbe2[4 * q + 3];
        reinterpret_cast<float4*>(op)[q] = o;
    }
}

extern "C" void kernel_launch(void* const* d_in, const int* in_sizes, int n_in,
                              void* d_out, int out_size) {
    const float* x         = (const float*)d_in[0];
    const float* adjacency = (const float*)d_in[1];
    const float* W1        = (const float*)d_in[2];
    const float* b1        = (const float*)d_in[3];
    const float* W2        = (const float*)d_in[4];
    const float* b2        = (const float*)d_in[5];
    const float* g1        = (const float*)d_in[6];
    const float* be1       = (const float*)d_in[7];
    const float* g2        = (const float*)d_in[8];
    const float* be2       = (const float*)d_in[9];
    float* out = (float*)d_out;

    int nrows = in_sizes[0] / D8;  // B*TF*C rows of D=8

    gnn_precompute_kernel<<<1, 1024>>>(adjacency, W1, b1, W2, b2);

    int blocks = (nrows + 255) / 256;
    gnn_main_kernel<<<blocks, 256>>>(x, g1, be1, g2, be2, out, nrows);
}

// round 5
// speedup vs baseline: 1.2702x; 1.2702x over previous
#include <cuda_runtime.h>
#include <cuda_bf16.h>

#define C32 32
#define D8  8

typedef unsigned long long ull;

// Precomputed folded matrices (device scratch; no allocation).
__device__ __align__(16) float g_M1T[D8 * C32];   // M1T[d][i] = sum_j A[i][j]*W1[j][d]
__device__ __align__(16) float g_c1[C32];         // c1[i]     = sum_j A[i][j]*b1[j]
__device__ __align__(16) float g_G2T[C32 * C32];  // G2T[k][i] = g1[k] * sum_j A[i][j]*W2[j][k]
__device__ __align__(16) float g_c2p[C32];        // c2'[i]    = A.b2[i] + sum_k be1[k]*M2T[k][i]
__device__ __align__(16) float g_colsum[C32];     // colsum[i] = sum_k G2T[k][i]

// ---- packed f32x2 helpers (Blackwell; PTX-only FFMA2/FADD2/FMUL2) ----
__device__ __forceinline__ ull pk2(float lo, float hi) {
    ull r;
    asm("mov.b64 %0, {%1, %2};" : "=l"(r) : "f"(lo), "f"(hi));
    return r;
}
__device__ __forceinline__ void upk2(ull v, float& lo, float& hi) {
    asm("mov.b64 {%0, %1}, %2;" : "=f"(lo), "=f"(hi) : "l"(v));
}
__device__ __forceinline__ void fma2(ull& d, ull a, ull b) {
    asm("fma.rn.f32x2 %0, %1, %2, %0;" : "+l"(d) : "l"(a), "l"(b));
}
__device__ __forceinline__ void add2(ull& d, ull a) {
    asm("add.rn.f32x2 %0, %0, %1;" : "+l"(d) : "l"(a));
}
__device__ __forceinline__ void mul2(ull& d, ull a, ull b) {
    asm("mul.rn.f32x2 %0, %1, %2;" : "=l"(d) : "l"(a), "l"(b));
}

// ============================================================================
// Precompute: normalized adjacency folded into both layers, PLUS fold of
// LN1's affine (g1, be1) into the layer-2 matrix/bias:
//   v[k] = (u[k]-m)*r*g1[k] + be1[k]
//   h2[i] = c2[i] + sum_k v[k]*M2T[k][i]
//         = c2'[i] + r*( sum_k u[k]*G2T[k][i]  -  m*colsum[i] )
// ============================================================================
__global__ void gnn_precompute_kernel(const float* __restrict__ adjacency,
                                      const float* __restrict__ W1,
                                      const float* __restrict__ b1,
                                      const float* __restrict__ W2,
                                      const float* __restrict__ b2,
                                      const float* __restrict__ g1,
                                      const float* __restrict__ be1) {
    __shared__ float A[C32][C32];
    __shared__ float dis[C32];
    __shared__ float Ms[C32][C32];   // M2T[k][i]
    __shared__ float Gs[C32][C32];   // G2T[k][i]
    int t = threadIdx.x;
    int i = t >> 5;
    int j = t & 31;

    float a = adjacency[i * C32 + j] + (i == j ? 1.0f : 0.0f);
    A[i][j] = a;
    __syncthreads();

    if (j == 0) {
        float s = 0.0f;
        #pragma unroll
        for (int k = 0; k < C32; k++) s += A[i][k];
        dis[i] = rsqrtf(s + 1e-6f);
    }
    __syncthreads();
    float na = dis[i] * A[i][j] * dis[j];
    __syncthreads();
    A[i][j] = na;   // A is now norm_adj
    __syncthreads();

    // M2T[k][i] for k = j
    {
        int k = j;
        float s = 0.0f;
        #pragma unroll
        for (int jj = 0; jj < C32; jj++) s += A[i][jj] * W2[jj * C32 + k];
        Ms[k][i] = s;
        float g = g1[k] * s;
        Gs[k][i] = g;
        g_G2T[k * C32 + i] = g;
    }
    // M1T[d][i]
    if (t < C32 * D8) {
        int ii = t >> 3;
        int d  = t & 7;
        float s = 0.0f;
        #pragma unroll
        for (int jj = 0; jj < C32; jj++) s += A[ii][jj] * W1[jj * D8 + d];
        g_M1T[d * C32 + ii] = s;
    }
    // c1
    if (t < C32) {
        float s1 = 0.0f;
        #pragma unroll
        for (int jj = 0; jj < C32; jj++) s1 += A[t][jj] * b1[jj];
        g_c1[t] = s1;
    }
    __syncthreads();

    // colsum[i], c2'[i]
    if (t < C32) {
        float cs = 0.0f, cp = 0.0f, c2 = 0.0f;
        #pragma unroll
        for (int k = 0; k < C32; k++) {
            cs += Gs[k][t];
            cp += be1[k] * Ms[k][t];
            c2 += A[t][k] * b2[k];
        }
        g_colsum[t] = cs;
        g_c2p[t] = c2 + cp;
    }
}

// ============================================================================
// Main fused kernel: one (bt,c) row per thread, 128 threads/block.
//   h1  = x@M1 + c1 ; u = relu(h1); (m,r) = LN stats of u
//   acc = u@G2 ; h2 = c2' + r*(acc - m*colsum)
//   out = LN2(relu(h2)) * g2 + be2   (coalesced via warp-local smem transpose)
// All matrix reads are LDS.128 (broadcast, conflict-free); all FMA packed f32x2.
// ============================================================================
__global__ __launch_bounds__(128) void gnn_main_kernel(
    const float* __restrict__ x,
    const float* __restrict__ g2, const float* __restrict__ be2,
    float* __restrict__ out, int nrows) {

    __shared__ __align__(16) float sM1T[D8 * C32];
    __shared__ __align__(16) float sc1[C32];
    __shared__ __align__(16) float sG2T[C32 * C32];
    __shared__ __align__(16) float sc2p[C32];
    __shared__ __align__(16) float scol[C32];
    __shared__ __align__(16) float sg2[C32], sbe2[C32];
    __shared__ __align__(16) float stg[4][32 * 36];   // per-warp staging, pitch 36

    int t = threadIdx.x;
    // cooperative shared fill (128 threads)
    ((float4*)sG2T)[t]       = ((const float4*)g_G2T)[t];
    ((float4*)sG2T)[t + 128] = ((const float4*)g_G2T)[t + 128];
    if (t < 64) ((float4*)sM1T)[t] = ((const float4*)g_M1T)[t];
    else if (t < 72)  ((float4*)sc1)[t - 64]  = ((const float4*)g_c1)[t - 64];
    else if (t < 80)  ((float4*)sc2p)[t - 72] = ((const float4*)g_c2p)[t - 72];
    else if (t < 88)  ((float4*)scol)[t - 80] = ((const float4*)g_colsum)[t - 80];
    else if (t < 96)  ((float4*)sg2)[t - 88]  = ((const float4*)g2)[t - 88];
    else if (t < 104) ((float4*)sbe2)[t - 96] = ((const float4*)be2)[t - 96];
    __syncthreads();

    int row = blockIdx.x * 128 + t;
    bool active = (row < nrows);
    int w = t >> 5, l = t & 31;

    ull h[16];    // layer1 accum / relu'd u (packed)
    ull acc[16];  // layer2 accum / final out values (packed)

    if (active) {
        // ---- load x row ----
        const float4* xv = reinterpret_cast<const float4*>(x + (size_t)row * D8);
        float4 xa = xv[0];
        float4 xb = xv[1];
        float xr[8] = {xa.x, xa.y, xa.z, xa.w, xb.x, xb.y, xb.z, xb.w};

        // ---- layer 1: h = c1 + x@M1T ----
        {
            const ulonglong2* cv = reinterpret_cast<const ulonglong2*>(sc1);
            #pragma unroll
            for (int q = 0; q < 8; q++) { ulonglong2 c = cv[q]; h[2*q] = c.x; h[2*q+1] = c.y; }
        }
        #pragma unroll
        for (int d = 0; d < D8; d++) {
            ull ad = pk2(xr[d], xr[d]);
            const ulonglong2* mr = reinterpret_cast<const ulonglong2*>(sM1T + d * C32);
            #pragma unroll
            for (int q = 0; q < 8; q++) {
                ulonglong2 mm = mr[q];
                fma2(h[2*q],     ad, mm.x);
                fma2(h[2*q+1],   ad, mm.y);
            }
        }

        // ---- relu + packed LN1 stats ----
        ull sp = 0ULL, ssp = 0ULL;
        #pragma unroll
        for (int i = 0; i < 16; i++) {
            float lo, hi;
            upk2(h[i], lo, hi);
            lo = fmaxf(lo, 0.0f);
            hi = fmaxf(hi, 0.0f);
            h[i] = pk2(lo, hi);
            add2(sp, h[i]);
            fma2(ssp, h[i], h[i]);
        }
        float s0, s1, q0, q1;
        upk2(sp, s0, s1); upk2(ssp, q0, q1);
        float m  = (s0 + s1) * (1.0f / 32.0f);
        float vv = (q0 + q1) * (1.0f / 32.0f) - m * m;
        float r  = rsqrtf(vv + 1e-5f);

        // ---- layer 2: acc = u @ G2T ----
        #pragma unroll
        for (int i = 0; i < 16; i++) acc[i] = 0ULL;
        #pragma unroll
        for (int p = 0; p < 16; p++) {
            float u0, u1;
            upk2(h[p], u0, u1);
            ull a0 = pk2(u0, u0);
            ull a1 = pk2(u1, u1);
            const ulonglong2* r0 = reinterpret_cast<const ulonglong2*>(sG2T + (2*p)     * C32);
            const ulonglong2* r1 = reinterpret_cast<const ulonglong2*>(sG2T + (2*p + 1) * C32);
            #pragma unroll
            for (int q = 0; q < 8; q++) {
                ulonglong2 m0 = r0[q];
                fma2(acc[2*q],   a0, m0.x);
                fma2(acc[2*q+1], a0, m0.y);
            }
            #pragma unroll
            for (int q = 0; q < 8; q++) {
                ulonglong2 m1 = r1[q];
                fma2(acc[2*q],   a1, m1.x);
                fma2(acc[2*q+1], a1, m1.y);
            }
        }

        // ---- h2 = c2' + r*(acc - m*colsum) ----
        ull nm = pk2(-m, -m);
        ull rp = pk2(r, r);
        {
            const ulonglong2* cv = reinterpret_cast<const ulonglong2*>(sc2p);
            const ulonglong2* kv = reinterpret_cast<const ulonglong2*>(scol);
            #pragma unroll
            for (int q = 0; q < 8; q++) {
                ulonglong2 cc = cv[q];
                ulonglong2 kk = kv[q];
                fma2(acc[2*q],   nm, kk.x);
                fma2(acc[2*q+1], nm, kk.y);
                ull t0 = cc.x; fma2(t0, rp, acc[2*q]);   acc[2*q]   = t0;
                ull t1 = cc.y; fma2(t1, rp, acc[2*q+1]); acc[2*q+1] = t1;
            }
        }

        // ---- relu + packed LN2 stats ----
        ull sp2 = 0ULL, ssp2 = 0ULL;
        #pragma unroll
        for (int i = 0; i < 16; i++) {
            float lo, hi;
            upk2(acc[i], lo, hi);
            lo = fmaxf(lo, 0.0f);
            hi = fmaxf(hi, 0.0f);
            acc[i] = pk2(lo, hi);
            add2(sp2, acc[i]);
            fma2(ssp2, acc[i], acc[i]);
        }
        float t0, t1, u0, u1;
        upk2(sp2, t0, t1); upk2(ssp2, u0, u1);
        float m2  = (t0 + t1) * (1.0f / 32.0f);
        float vv2 = (u0 + u1) * (1.0f / 32.0f) - m2 * m2;
        float r2  = rsqrtf(vv2 + 1e-5f);

        // ---- epilogue: out = relu(h2)*(r2*g2) + (be2 - m2*r2*g2), packed ----
        ull r2p  = pk2(r2, r2);
        ull mr2p = pk2(-m2 * r2, -m2 * r2);
        {
            const ulonglong2* gv = reinterpret_cast<const ulonglong2*>(sg2);
            const ulonglong2* bv = reinterpret_cast<const ulonglong2*>(sbe2);
            #pragma unroll
            for (int q = 0; q < 8; q++) {
                ulonglong2 gg = gv[q];
                ulonglong2 bb = bv[q];
                ull w0, w1;
                mul2(w0, gg.x, r2p);
                mul2(w1, gg.y, r2p);
                ull o0 = bb.x; fma2(o0, mr2p, gg.x); fma2(o0, acc[2*q],   w0);
                ull o1 = bb.y; fma2(o1, mr2p, gg.y); fma2(o1, acc[2*q+1], w1);
                acc[2*q]   = o0;
                acc[2*q+1] = o1;
            }
        }

        // ---- stage into padded smem tile (conflict-free) ----
        float* buf = &stg[w][l * 36];
        #pragma unroll
        for (int q = 0; q < 8; q++) {
            float a0, a1, a2, a3;
            upk2(acc[2*q],   a0, a1);
            upk2(acc[2*q+1], a2, a3);
            *reinterpret_cast<float4*>(buf + q * 4) = make_float4(a0, a1, a2, a3);
        }
    }
    __syncwarp();

    // ---- coalesced store: warp writes its 32 rows x 32 cols contiguously ----
    {
        const float* wb = &stg[w][0];
        int rowbase = blockIdx.x * 128 + w * 32;
        float4* odst = reinterpret_cast<float4*>(out + (size_t)rowbase * C32);
        #pragma unroll
        for (int q = 0; q < 8; q++) {
            int idx4 = l + q * 32;
            int rr = idx4 >> 3;
            int c4 = idx4 & 7;
            if (rowbase + rr < nrows) {
                float4 v = *reinterpret_cast<const float4*>(wb + rr * 36 + c4 * 4);
                odst[idx4] = v;
            }
        }
    }
}

extern "C" void kernel_launch(void* const* d_in, const int* in_sizes, int n_in,
                              void* d_out, int out_size) {
    const float* x         = (const float*)d_in[0];
    const float* adjacency = (const float*)d_in[1];
    const float* W1        = (const float*)d_in[2];
    const float* b1        = (const float*)d_in[3];
    const float* W2        = (const float*)d_in[4];
    const float* b2        = (const float*)d_in[5];
    const float* g1        = (const float*)d_in[6];
    const float* be1       = (const float*)d_in[7];
    const float* g2        = (const float*)d_in[8];
    const float* be2       = (const float*)d_in[9];
    float* out = (float*)d_out;

    int nrows = in_sizes[0] / D8;  // B*TF*C rows of D=8

    gnn_precompute_kernel<<<1, 1024>>>(adjacency, W1, b1, W2, b2, g1, be1);

    int blocks = (nrows + 127) / 128;
    gnn_main_kernel<<<blocks, 128>>>(x, g2, be2, out, nrows);
}

// round 6
// speedup vs baseline: 1.7214x; 1.3553x over previous
#include <cuda_runtime.h>
#include <cuda_bf16.h>

#define C32 32
#define D8  8

typedef unsigned long long ull;

// Precomputed folded matrices (device scratch; no allocation).
__device__ __align__(16) float g_M1T[D8 * C32];   // M1T[d][i] = sum_j A[i][j]*W1[j][d]
__device__ __align__(16) float g_c1[C32];         // c1[i]     = sum_j A[i][j]*b1[j]
__device__ __align__(16) float g_G2T[C32 * C32];  // G2T[k][i] = g1[k]*sum_j A[i][j]*W2[j][k]
__device__ __align__(16) float g_c2p[C32];        // c2'[i]    = A.b2[i] + sum_k be1[k]*M2T[k][i]
__device__ __align__(16) float g_colsum[C32];     // colsum[i] = sum_k G2T[k][i]

// ---- packed f32x2 helpers (Blackwell; PTX-only FFMA2/FADD2/FMUL2) ----
__device__ __forceinline__ ull pk2(float lo, float hi) {
    ull r;
    asm("mov.b64 %0, {%1, %2};" : "=l"(r) : "f"(lo), "f"(hi));
    return r;
}
__device__ __forceinline__ void upk2(ull v, float& lo, float& hi) {
    asm("mov.b64 {%0, %1}, %2;" : "=f"(lo), "=f"(hi) : "l"(v));
}
__device__ __forceinline__ void fma2(ull& d, ull a, ull b) {
    asm("fma.rn.f32x2 %0, %1, %2, %0;" : "+l"(d) : "l"(a), "l"(b));
}
__device__ __forceinline__ void add2(ull& d, ull a) {
    asm("add.rn.f32x2 %0, %0, %1;" : "+l"(d) : "l"(a));
}
__device__ __forceinline__ void mul2(ull& d, ull a, ull b) {
    asm("mul.rn.f32x2 %0, %1, %2;" : "=l"(d) : "l"(a), "l"(b));
}

// ============================================================================
// Precompute: normalized adjacency folded into both layers, plus LN1 affine
// folded into layer 2 (see round-4 derivation).
// ============================================================================
__global__ void gnn_precompute_kernel(const float* __restrict__ adjacency,
                                      const float* __restrict__ W1,
                                      const float* __restrict__ b1,
                                      const float* __restrict__ W2,
                                      const float* __restrict__ b2,
                                      const float* __restrict__ g1,
                                      const float* __restrict__ be1) {
    __shared__ float A[C32][C32];
    __shared__ float dis[C32];
    __shared__ float Ms[C32][C32];   // M2T[k][i]
    __shared__ float Gs[C32][C32];   // G2T[k][i]
    int t = threadIdx.x;
    int i = t >> 5;
    int j = t & 31;

    float a = adjacency[i * C32 + j] + (i == j ? 1.0f : 0.0f);
    A[i][j] = a;
    __syncthreads();

    if (j == 0) {
        float s = 0.0f;
        #pragma unroll
        for (int k = 0; k < C32; k++) s += A[i][k];
        dis[i] = rsqrtf(s + 1e-6f);
    }
    __syncthreads();
    float na = dis[i] * A[i][j] * dis[j];
    __syncthreads();
    A[i][j] = na;   // A is now norm_adj
    __syncthreads();

    // M2T[k][i] for k = j
    {
        int k = j;
        float s = 0.0f;
        #pragma unroll
        for (int jj = 0; jj < C32; jj++) s += A[i][jj] * W2[jj * C32 + k];
        Ms[k][i] = s;
        float g = g1[k] * s;
        Gs[k][i] = g;
        g_G2T[k * C32 + i] = g;
    }
    // M1T[d][i]
    if (t < C32 * D8) {
        int ii = t >> 3;
        int d  = t & 7;
        float s = 0.0f;
        #pragma unroll
        for (int jj = 0; jj < C32; jj++) s += A[ii][jj] * W1[jj * D8 + d];
        g_M1T[d * C32 + ii] = s;
    }
    // c1
    if (t < C32) {
        float s1 = 0.0f;
        #pragma unroll
        for (int jj = 0; jj < C32; jj++) s1 += A[t][jj] * b1[jj];
        g_c1[t] = s1;
    }
    __syncthreads();

    // colsum[i], c2'[i]
    if (t < C32) {
        float cs = 0.0f, cp = 0.0f, c2 = 0.0f;
        #pragma unroll
        for (int k = 0; k < C32; k++) {
            cs += Gs[k][t];
            cp += be1[k] * Ms[k][t];
            c2 += A[t][k] * b2[k];
        }
        g_colsum[t] = cs;
        g_c2p[t] = c2 + cp;
    }
}

// ---- per-row helpers ----
__device__ __forceinline__ void relu_stats(ull* v, float& m, float& r) {
    ull sp = 0ULL, ssp = 0ULL;
    #pragma unroll
    for (int i = 0; i < 16; i++) {
        float lo, hi;
        upk2(v[i], lo, hi);
        lo = fmaxf(lo, 0.0f);
        hi = fmaxf(hi, 0.0f);
        v[i] = pk2(lo, hi);
        add2(sp, v[i]);
        fma2(ssp, v[i], v[i]);
    }
    float s0, s1, q0, q1;
    upk2(sp, s0, s1); upk2(ssp, q0, q1);
    m = (s0 + s1) * (1.0f / 32.0f);
    float vv = (q0 + q1) * (1.0f / 32.0f) - m * m;
    r = rsqrtf(vv + 1e-5f);
}

__device__ __forceinline__ void fold_ln1(ull* acc, float m, float r,
                                         const float* sc2p, const float* scol) {
    ull nm = pk2(-m, -m);
    ull rp = pk2(r, r);
    const ulonglong2* cv = reinterpret_cast<const ulonglong2*>(sc2p);
    const ulonglong2* kv = reinterpret_cast<const ulonglong2*>(scol);
    #pragma unroll
    for (int q = 0; q < 8; q++) {
        ulonglong2 cc = cv[q];
        ulonglong2 kk = kv[q];
        fma2(acc[2*q],   nm, kk.x);
        fma2(acc[2*q+1], nm, kk.y);
        ull t0 = cc.x; fma2(t0, rp, acc[2*q]);   acc[2*q]   = t0;
        ull t1 = cc.y; fma2(t1, rp, acc[2*q+1]); acc[2*q+1] = t1;
    }
}

__device__ __forceinline__ void epilogue_stage(ull* acc, float m2, float r2,
                                               const float* sg2, const float* sbe2,
                                               float* buf) {
    ull r2p  = pk2(r2, r2);
    ull mr2p = pk2(-m2 * r2, -m2 * r2);
    const ulonglong2* gv = reinterpret_cast<const ulonglong2*>(sg2);
    const ulonglong2* bv = reinterpret_cast<const ulonglong2*>(sbe2);
    #pragma unroll
    for (int q = 0; q < 8; q++) {
        ulonglong2 gg = gv[q];
        ulonglong2 bb = bv[q];
        ull w0, w1;
        mul2(w0, gg.x, r2p);
        mul2(w1, gg.y, r2p);
        ull o0 = bb.x; fma2(o0, mr2p, gg.x); fma2(o0, acc[2*q],   w0);
        ull o1 = bb.y; fma2(o1, mr2p, gg.y); fma2(o1, acc[2*q+1], w1);
        float a0, a1, a2, a3;
        upk2(o0, a0, a1);
        upk2(o1, a2, a3);
        *reinterpret_cast<float4*>(buf + q * 4) = make_float4(a0, a1, a2, a3);
    }
}

// ============================================================================
// Main fused kernel: 128 threads/block, TWO rows per thread (rows t and t+128
// of a 256-row block tile) so every broadcast matrix LDS is amortized over 2
// rows. All matrix reads LDS.128; all math packed f32x2; coalesced stores via
// padded warp-local smem transpose (buffer reused for the two tiles).
// ============================================================================
__global__ __launch_bounds__(128) void gnn_main_kernel(
    const float* __restrict__ x,
    const float* __restrict__ g2, const float* __restrict__ be2,
    float* __restrict__ out, int nrows) {

    __shared__ __align__(16) float sM1T[D8 * C32];
    __shared__ __align__(16) float sc1[C32];
    __shared__ __align__(16) float sG2T[C32 * C32];
    __shared__ __align__(16) float sc2p[C32];
    __shared__ __align__(16) float scol[C32];
    __shared__ __align__(16) float sg2[C32], sbe2[C32];
    __shared__ __align__(16) float stg[4][32 * 36];   // per-warp staging, pitch 36

    int t = threadIdx.x;
    // cooperative shared fill (128 threads)
    ((float4*)sG2T)[t]       = ((const float4*)g_G2T)[t];
    ((float4*)sG2T)[t + 128] = ((const float4*)g_G2T)[t + 128];
    if (t < 64) ((float4*)sM1T)[t] = ((const float4*)g_M1T)[t];
    else if (t < 72)  ((float4*)sc1)[t - 64]  = ((const float4*)g_c1)[t - 64];
    else if (t < 80)  ((float4*)sc2p)[t - 72] = ((const float4*)g_c2p)[t - 72];
    else if (t < 88)  ((float4*)scol)[t - 80] = ((const float4*)g_colsum)[t - 80];
    else if (t < 96)  ((float4*)sg2)[t - 88]  = ((const float4*)g2)[t - 88];
    else if (t < 104) ((float4*)sbe2)[t - 96] = ((const float4*)be2)[t - 96];
    __syncthreads();

    int w = t >> 5, l = t & 31;
    int rowA = blockIdx.x * 256 + t;
    int rowB = rowA + 128;
    bool actA = (rowA < nrows);
    bool actB = (rowB < nrows);

    ull ha[16], hb[16];   // layer1 accum / relu'd u
    ull aa[16], ab[16];   // layer2 accum

    // ---- load x rows ----
    float xra[8] = {0,0,0,0,0,0,0,0}, xrb[8] = {0,0,0,0,0,0,0,0};
    if (actA) {
        const float4* xv = reinterpret_cast<const float4*>(x + (size_t)rowA * D8);
        float4 a0 = xv[0], a1 = xv[1];
        xra[0]=a0.x; xra[1]=a0.y; xra[2]=a0.z; xra[3]=a0.w;
        xra[4]=a1.x; xra[5]=a1.y; xra[6]=a1.z; xra[7]=a1.w;
    }
    if (actB) {
        const float4* xv = reinterpret_cast<const float4*>(x + (size_t)rowB * D8);
        float4 b0 = xv[0], b1 = xv[1];
        xrb[0]=b0.x; xrb[1]=b0.y; xrb[2]=b0.z; xrb[3]=b0.w;
        xrb[4]=b1.x; xrb[5]=b1.y; xrb[6]=b1.z; xrb[7]=b1.w;
    }

    // ---- layer 1 (both rows, shared matrix loads) ----
    {
        const ulonglong2* cv = reinterpret_cast<const ulonglong2*>(sc1);
        #pragma unroll
        for (int q = 0; q < 8; q++) {
            ulonglong2 c = cv[q];
            ha[2*q] = c.x; ha[2*q+1] = c.y;
            hb[2*q] = c.x; hb[2*q+1] = c.y;
        }
    }
    #pragma unroll
    for (int d = 0; d < D8; d++) {
        ull adA = pk2(xra[d], xra[d]);
        ull adB = pk2(xrb[d], xrb[d]);
        const ulonglong2* mr = reinterpret_cast<const ulonglong2*>(sM1T + d * C32);
        #pragma unroll
        for (int q = 0; q < 8; q++) {
            ulonglong2 mm = mr[q];
            fma2(ha[2*q],   adA, mm.x);
            fma2(ha[2*q+1], adA, mm.y);
            fma2(hb[2*q],   adB, mm.x);
            fma2(hb[2*q+1], adB, mm.y);
        }
    }

    // ---- relu + LN1 stats ----
    float mA, rA, mB, rB;
    relu_stats(ha, mA, rA);
    relu_stats(hb, mB, rB);

    // ---- layer 2 (both rows, shared matrix loads) ----
    #pragma unroll
    for (int i = 0; i < 16; i++) { aa[i] = 0ULL; ab[i] = 0ULL; }
    #pragma unroll
    for (int p = 0; p < 16; p++) {
        float u0A, u1A, u0B, u1B;
        upk2(ha[p], u0A, u1A);
        upk2(hb[p], u0B, u1B);
        ull a0A = pk2(u0A, u0A), a1A = pk2(u1A, u1A);
        ull a0B = pk2(u0B, u0B), a1B = pk2(u1B, u1B);
        const ulonglong2* r0 = reinterpret_cast<const ulonglong2*>(sG2T + (2*p)     * C32);
        const ulonglong2* r1 = reinterpret_cast<const ulonglong2*>(sG2T + (2*p + 1) * C32);
        #pragma unroll
        for (int q = 0; q < 8; q++) {
            ulonglong2 m0 = r0[q];
            fma2(aa[2*q],   a0A, m0.x);
            fma2(aa[2*q+1], a0A, m0.y);
            fma2(ab[2*q],   a0B, m0.x);
            fma2(ab[2*q+1], a0B, m0.y);
        }
        #pragma unroll
        for (int q = 0; q < 8; q++) {
            ulonglong2 m1 = r1[q];
            fma2(aa[2*q],   a1A, m1.x);
            fma2(aa[2*q+1], a1A, m1.y);
            fma2(ab[2*q],   a1B, m1.x);
            fma2(ab[2*q+1], a1B, m1.y);
        }
    }

    // ---- fold LN1, relu + LN2, epilogue, stage+store (tile A then tile B) ----
    fold_ln1(aa, mA, rA, sc2p, scol);
    fold_ln1(ab, mB, rB, sc2p, scol);

    float m2A, r2A, m2B, r2B;
    relu_stats(aa, m2A, r2A);
    relu_stats(ab, m2B, r2B);

    float* buf = &stg[w][l * 36];
    const float* wb = &stg[w][0];

    // --- tile A ---
    if (actA) epilogue_stage(aa, m2A, r2A, sg2, sbe2, buf);
    __syncwarp();
    {
        int rowbase = blockIdx.x * 256 + w * 32;
        float4* odst = reinterpret_cast<float4*>(out + (size_t)rowbase * C32);
        #pragma unroll
        for (int q = 0; q < 8; q++) {
            int idx4 = l + q * 32;
            int rr = idx4 >> 3;
            int c4 = idx4 & 7;
            if (rowbase + rr < nrows) {
                float4 v = *reinterpret_cast<const float4*>(wb + rr * 36 + c4 * 4);
                odst[idx4] = v;
            }
        }
    }
    __syncwarp();

    // --- tile B (reuse buffer) ---
    if (actB) epilogue_stage(ab, m2B, r2B, sg2, sbe2, buf);
    __syncwarp();
    {
        int rowbase = blockIdx.x * 256 + 128 + w * 32;
        float4* odst = reinterpret_cast<float4*>(out + (size_t)rowbase * C32);
        #pragma unroll
        for (int q = 0; q < 8; q++) {
            int idx4 = l + q * 32;
            int rr = idx4 >> 3;
            int c4 = idx4 & 7;
            if (rowbase + rr < nrows) {
                float4 v = *reinterpret_cast<const float4*>(wb + rr * 36 + c4 * 4);
                odst[idx4] = v;
            }
        }
    }
}

extern "C" void kernel_launch(void* const* d_in, const int* in_sizes, int n_in,
                              void* d_out, int out_size) {
    const float* x         = (const float*)d_in[0];
    const float* adjacency = (const float*)d_in[1];
    const float* W1        = (const float*)d_in[2];
    const float* b1        = (const float*)d_in[3];
    const float* W2        = (const float*)d_in[4];
    const float* b2        = (const float*)d_in[5];
    const float* g1        = (const float*)d_in[6];
    const float* be1       = (const float*)d_in[7];
    const float* g2        = (const float*)d_in[8];
    const float* be2       = (const float*)d_in[9];
    float* out = (float*)d_out;

    int nrows = in_sizes[0] / D8;  // B*TF*C rows of D=8

    gnn_precompute_kernel<<<1, 1024>>>(adjacency, W1, b1, W2, b2, g1, be1);

    int blocks = (nrows + 255) / 256;   // 256 rows per block (2 per thread)
    gnn_main_kernel<<<blocks, 128>>>(x, g2, be2, out, nrows);
}

// round 7
// speedup vs baseline: 1.9822x; 1.1515x over previous
#include <cuda_runtime.h>
#include <cuda_bf16.h>

#define C32 32
#define D8  8

typedef unsigned long long ull;

// ---- device scratch written by precompute (sources for constant-memory copies) ----
__device__ __align__(16) float g_M1T[D8 * C32];    // M1T[d][i]
__device__ __align__(16) float g_c1[C32];
__device__ __align__(16) float g_G2A[C32 * 16];    // G2T[k][0..15]  (k-major)
__device__ __align__(16) float g_G2B[C32 * 16];    // G2T[k][16..31]
__device__ __align__(16) float g_c2p[C32];
__device__ __align__(16) float g_colsum[C32];

// ---- constant-memory mirrors (separate LDC port; zero smem-crossbar cost) ----
__constant__ __align__(16) float cM1T[D8 * C32];
__constant__ __align__(16) float cc1[C32];
__constant__ __align__(16) float cG2A[C32 * 16];
__constant__ __align__(16) float cc2p[C32];
__constant__ __align__(16) float ccol[C32];
__constant__ __align__(16) float cg2[C32];
__constant__ __align__(16) float cbe2[C32];

// ---- packed f32x2 helpers (Blackwell FFMA2/FADD2/FMUL2, PTX-only) ----
__device__ __forceinline__ ull pk2(float lo, float hi) {
    ull r;
    asm("mov.b64 %0, {%1, %2};" : "=l"(r) : "f"(lo), "f"(hi));
    return r;
}
__device__ __forceinline__ void upk2(ull v, float& lo, float& hi) {
    asm("mov.b64 {%0, %1}, %2;" : "=f"(lo), "=f"(hi) : "l"(v));
}
__device__ __forceinline__ void fma2(ull& d, ull a, ull b) {
    asm("fma.rn.f32x2 %0, %1, %2, %0;" : "+l"(d) : "l"(a), "l"(b));
}
__device__ __forceinline__ void add2(ull& d, ull a) {
    asm("add.rn.f32x2 %0, %0, %1;" : "+l"(d) : "l"(a));
}
__device__ __forceinline__ void mul2(ull& d, ull a, ull b) {
    asm("mul.rn.f32x2 %0, %1, %2;" : "=l"(d) : "l"(a), "l"(b));
}

// ============================================================================
// Precompute (unchanged math): normalized adjacency folded into both layers,
// LN1 affine folded into layer 2. Writes split G2A/G2B for the port split.
// ============================================================================
__global__ void gnn_precompute_kernel(const float* __restrict__ adjacency,
                                      const float* __restrict__ W1,
                                      const float* __restrict__ b1,
                                      const float* __restrict__ W2,
                                      const float* __restrict__ b2,
                                      const float* __restrict__ g1,
                                      const float* __restrict__ be1) {
    __shared__ float A[C32][C32];
    __shared__ float dis[C32];
    __shared__ float Ms[C32][C32];   // M2T[k][i]
    __shared__ float Gs[C32][C32];   // G2T[k][i]
    int t = threadIdx.x;
    int i = t >> 5;
    int j = t & 31;

    float a = adjacency[i * C32 + j] + (i == j ? 1.0f : 0.0f);
    A[i][j] = a;
    __syncthreads();

    if (j == 0) {
        float s = 0.0f;
        #pragma unroll
        for (int k = 0; k < C32; k++) s += A[i][k];
        dis[i] = rsqrtf(s + 1e-6f);
    }
    __syncthreads();
    float na = dis[i] * A[i][j] * dis[j];
    __syncthreads();
    A[i][j] = na;   // A is now norm_adj
    __syncthreads();

    // M2T[k][i] for k = j
    {
        int k = j;
        float s = 0.0f;
        #pragma unroll
        for (int jj = 0; jj < C32; jj++) s += A[i][jj] * W2[jj * C32 + k];
        Ms[k][i] = s;
        float g = g1[k] * s;
        Gs[k][i] = g;
        if (i < 16) g_G2A[k * 16 + i] = g;
        else        g_G2B[k * 16 + (i - 16)] = g;
    }
    // M1T[d][i]
    if (t < C32 * D8) {
        int ii = t >> 3;
        int d  = t & 7;
        float s = 0.0f;
        #pragma unroll
        for (int jj = 0; jj < C32; jj++) s += A[ii][jj] * W1[jj * D8 + d];
        g_M1T[d * C32 + ii] = s;
    }
    // c1
    if (t < C32) {
        float s1 = 0.0f;
        #pragma unroll
        for (int jj = 0; jj < C32; jj++) s1 += A[t][jj] * b1[jj];
        g_c1[t] = s1;
    }
    __syncthreads();

    // colsum[i], c2'[i]
    if (t < C32) {
        float cs = 0.0f, cp = 0.0f, c2 = 0.0f;
        #pragma unroll
        for (int k = 0; k < C32; k++) {
            cs += Gs[k][t];
            cp += be1[k] * Ms[k][t];
            c2 += A[t][k] * b2[k];
        }
        g_colsum[t] = cs;
        g_c2p[t] = c2 + cp;
    }
}

// ---- per-row helpers ----
__device__ __forceinline__ void relu_stats(ull* v, float& m, float& r) {
    ull sp = 0ULL, ssp = 0ULL;
    #pragma unroll
    for (int i = 0; i < 16; i++) {
        float lo, hi;
        upk2(v[i], lo, hi);
        lo = fmaxf(lo, 0.0f);
        hi = fmaxf(hi, 0.0f);
        v[i] = pk2(lo, hi);
        add2(sp, v[i]);
        fma2(ssp, v[i], v[i]);
    }
    float s0, s1, q0, q1;
    upk2(sp, s0, s1); upk2(ssp, q0, q1);
    m = (s0 + s1) * (1.0f / 32.0f);
    float vv = (q0 + q1) * (1.0f / 32.0f) - m * m;
    r = rsqrtf(vv + 1e-5f);
}

__device__ __forceinline__ void fold_ln1(ull* acc, float m, float r) {
    ull nm = pk2(-m, -m);
    ull rp = pk2(r, r);
    const ulonglong2* cv = reinterpret_cast<const ulonglong2*>(cc2p);
    const ulonglong2* kv = reinterpret_cast<const ulonglong2*>(ccol);
    #pragma unroll
    for (int q = 0; q < 8; q++) {
        ulonglong2 cc = cv[q];
        ulonglong2 kk = kv[q];
        fma2(acc[2*q],   nm, kk.x);
        fma2(acc[2*q+1], nm, kk.y);
        ull t0 = cc.x; fma2(t0, rp, acc[2*q]);   acc[2*q]   = t0;
        ull t1 = cc.y; fma2(t1, rp, acc[2*q+1]); acc[2*q+1] = t1;
    }
}

__device__ __forceinline__ void epilogue_stage(ull* acc, float m2, float r2,
                                               float* buf) {
    ull r2p  = pk2(r2, r2);
    ull mr2p = pk2(-m2 * r2, -m2 * r2);
    const ulonglong2* gv = reinterpret_cast<const ulonglong2*>(cg2);
    const ulonglong2* bv = reinterpret_cast<const ulonglong2*>(cbe2);
    #pragma unroll
    for (int q = 0; q < 8; q++) {
        ulonglong2 gg = gv[q];
        ulonglong2 bb = bv[q];
        ull w0, w1;
        mul2(w0, gg.x, r2p);
        mul2(w1, gg.y, r2p);
        ull o0 = bb.x; fma2(o0, mr2p, gg.x); fma2(o0, acc[2*q],   w0);
        ull o1 = bb.y; fma2(o1, mr2p, gg.y); fma2(o1, acc[2*q+1], w1);
        float a0, a1, a2, a3;
        upk2(o0, a0, a1);
        upk2(o1, a2, a3);
        *reinterpret_cast<float4*>(buf + q * 4) = make_float4(a0, a1, a2, a3);
    }
}

// ============================================================================
// Main fused kernel: 128 threads/block, 2 rows/thread. Layer-2 matrix split:
// cols 0..15 via constant port (LDC), cols 16..31 via smem crossbar (LDS) —
// the two memory ports run in parallel with the fma pipe. Layer-1 matrix,
// biases, LN params all via constant port. smem: G2B half + store staging.
// ============================================================================
__global__ __launch_bounds__(128) void gnn_main_kernel(
    const float* __restrict__ x,
    float* __restrict__ out, int nrows) {

    __shared__ __align__(16) float sG2B[C32 * 16];
    __shared__ __align__(16) float stg[4][32 * 36];   // per-warp staging, pitch 36

    int t = threadIdx.x;
    ((float4*)sG2B)[t] = ((const float4*)g_G2B)[t];   // 512 floats = 128 float4
    __syncthreads();

    int w = t >> 5, l = t & 31;
    int rowA = blockIdx.x * 256 + t;
    int rowB = rowA + 128;
    bool actA = (rowA < nrows);
    bool actB = (rowB < nrows);

    ull ha[16], hb[16];   // layer1 accum / relu'd u
    ull aa[16], ab[16];   // layer2 accum

    // ---- load x rows ----
    float xra[8] = {0,0,0,0,0,0,0,0}, xrb[8] = {0,0,0,0,0,0,0,0};
    if (actA) {
        const float4* xv = reinterpret_cast<const float4*>(x + (size_t)rowA * D8);
        float4 a0 = xv[0], a1 = xv[1];
        xra[0]=a0.x; xra[1]=a0.y; xra[2]=a0.z; xra[3]=a0.w;
        xra[4]=a1.x; xra[5]=a1.y; xra[6]=a1.z; xra[7]=a1.w;
    }
    if (actB) {
        const float4* xv = reinterpret_cast<const float4*>(x + (size_t)rowB * D8);
        float4 b0 = xv[0], b1 = xv[1];
        xrb[0]=b0.x; xrb[1]=b0.y; xrb[2]=b0.z; xrb[3]=b0.w;
        xrb[4]=b1.x; xrb[5]=b1.y; xrb[6]=b1.z; xrb[7]=b1.w;
    }

    // ---- layer 1 (matrix + bias from constant port) ----
    {
        const ulonglong2* cv = reinterpret_cast<const ulonglong2*>(cc1);
        #pragma unroll
        for (int q = 0; q < 8; q++) {
            ulonglong2 c = cv[q];
            ha[2*q] = c.x; ha[2*q+1] = c.y;
            hb[2*q] = c.x; hb[2*q+1] = c.y;
        }
    }
    #pragma unroll
    for (int d = 0; d < D8; d++) {
        ull adA = pk2(xra[d], xra[d]);
        ull adB = pk2(xrb[d], xrb[d]);
        const ulonglong2* mr = reinterpret_cast<const ulonglong2*>(cM1T + d * C32);
        #pragma unroll
        for (int q = 0; q < 8; q++) {
            ulonglong2 mm = mr[q];
            fma2(ha[2*q],   adA, mm.x);
            fma2(ha[2*q+1], adA, mm.y);
            fma2(hb[2*q],   adB, mm.x);
            fma2(hb[2*q+1], adB, mm.y);
        }
    }

    // ---- relu + LN1 stats ----
    float mA, rA, mB, rB;
    relu_stats(ha, mA, rA);
    relu_stats(hb, mB, rB);

    // ---- layer 2: cols 0..15 from constant (acc[0..7]),
    //               cols 16..31 from smem (acc[8..15]) ----
    #pragma unroll
    for (int i = 0; i < 16; i++) { aa[i] = 0ULL; ab[i] = 0ULL; }
    #pragma unroll
    for (int p = 0; p < 16; p++) {
        float u0A, u1A, u0B, u1B;
        upk2(ha[p], u0A, u1A);
        upk2(hb[p], u0B, u1B);
        ull a0A = pk2(u0A, u0A), a1A = pk2(u1A, u1A);
        ull a0B = pk2(u0B, u0B), a1B = pk2(u1B, u1B);
        const ulonglong2* ca0 = reinterpret_cast<const ulonglong2*>(cG2A + (2*p)   * 16);
        const ulonglong2* ca1 = reinterpret_cast<const ulonglong2*>(cG2A + (2*p+1) * 16);
        const ulonglong2* sb0 = reinterpret_cast<const ulonglong2*>(sG2B + (2*p)   * 16);
        const ulonglong2* sb1 = reinterpret_cast<const ulonglong2*>(sG2B + (2*p+1) * 16);
        #pragma unroll
        for (int q = 0; q < 4; q++) {
            ulonglong2 m0 = ca0[q];
            fma2(aa[2*q],   a0A, m0.x);
            fma2(aa[2*q+1], a0A, m0.y);
            fma2(ab[2*q],   a0B, m0.x);
            fma2(ab[2*q+1], a0B, m0.y);
            ulonglong2 s0 = sb0[q];
            fma2(aa[8+2*q],   a0A, s0.x);
            fma2(aa[8+2*q+1], a0A, s0.y);
            fma2(ab[8+2*q],   a0B, s0.x);
            fma2(ab[8+2*q+1], a0B, s0.y);
        }
        #pragma unroll
        for (int q = 0; q < 4; q++) {
            ulonglong2 m1 = ca1[q];
            fma2(aa[2*q],   a1A, m1.x);
            fma2(aa[2*q+1], a1A, m1.y);
            fma2(ab[2*q],   a1B, m1.x);
            fma2(ab[2*q+1], a1B, m1.y);
            ulonglong2 s1 = sb1[q];
            fma2(aa[8+2*q],   a1A, s1.x);
            fma2(aa[8+2*q+1], a1A, s1.y);
            fma2(ab[8+2*q],   a1B, s1.x);
            fma2(ab[8+2*q+1], a1B, s1.y);
        }
    }

    // ---- fold LN1, relu + LN2 ----
    fold_ln1(aa, mA, rA);
    fold_ln1(ab, mB, rB);

    float m2A, r2A, m2B, r2B;
    relu_stats(aa, m2A, r2A);
    relu_stats(ab, m2B, r2B);

    float* buf = &stg[w][l * 36];
    const float* wb = &stg[w][0];

    // --- tile A: epilogue + coalesced store via padded smem transpose ---
    if (actA) epilogue_stage(aa, m2A, r2A, buf);
    __syncwarp();
    {
        int rowbase = blockIdx.x * 256 + w * 32;
        float4* odst = reinterpret_cast<float4*>(out + (size_t)rowbase * C32);
        #pragma unroll
        for (int q = 0; q < 8; q++) {
            int idx4 = l + q * 32;
            int rr = idx4 >> 3;
            int c4 = idx4 & 7;
            if (rowbase + rr < nrows) {
                float4 v = *reinterpret_cast<const float4*>(wb + rr * 36 + c4 * 4);
                odst[idx4] = v;
            }
        }
    }
    __syncwarp();

    // --- tile B (reuse buffer) ---
    if (actB) epilogue_stage(ab, m2B, r2B, buf);
    __syncwarp();
    {
        int rowbase = blockIdx.x * 256 + 128 + w * 32;
        float4* odst = reinterpret_cast<float4*>(out + (size_t)rowbase * C32);
        #pragma unroll
        for (int q = 0; q < 8; q++) {
            int idx4 = l + q * 32;
            int rr = idx4 >> 3;
            int c4 = idx4 & 7;
            if (rowbase + rr < nrows) {
                float4 v = *reinterpret_cast<const float4*>(wb + rr * 36 + c4 * 4);
                odst[idx4] = v;
            }
        }
    }
}

extern "C" void kernel_launch(void* const* d_in, const int* in_sizes, int n_in,
                              void* d_out, int out_size) {
    const float* x         = (const float*)d_in[0];
    const float* adjacency = (const float*)d_in[1];
    const float* W1        = (const float*)d_in[2];
    const float* b1        = (const float*)d_in[3];
    const float* W2        = (const float*)d_in[4];
    const float* b2        = (const float*)d_in[5];
    const float* g1        = (const float*)d_in[6];
    const float* be1       = (const float*)d_in[7];
    const float* g2        = (const float*)d_in[8];
    const float* be2       = (const float*)d_in[9];
    float* out = (float*)d_out;

    int nrows = in_sizes[0] / D8;  // B*TF*C rows of D=8

    gnn_precompute_kernel<<<1, 1024>>>(adjacency, W1, b1, W2, b2, g1, be1);

    // Populate constant memory from device scratch (D2D async memcpys;
    // graph-capturable memcpy nodes, no allocation).
    void *pM1T, *pc1, *pG2A, *pc2p, *pcol;
    cudaGetSymbolAddress(&pM1T, g_M1T);
    cudaGetSymbolAddress(&pc1,  g_c1);
    cudaGetSymbolAddress(&pG2A, g_G2A);
    cudaGetSymbolAddress(&pc2p, g_c2p);
    cudaGetSymbolAddress(&pcol, g_colsum);
    cudaMemcpyToSymbolAsync(cM1T, pM1T, D8 * C32 * sizeof(float), 0, cudaMemcpyDeviceToDevice, 0);
    cudaMemcpyToSymbolAsync(cc1,  pc1,  C32 * sizeof(float),      0, cudaMemcpyDeviceToDevice, 0);
    cudaMemcpyToSymbolAsync(cG2A, pG2A, C32 * 16 * sizeof(float), 0, cudaMemcpyDeviceToDevice, 0);
    cudaMemcpyToSymbolAsync(cc2p, pc2p, C32 * sizeof(float),      0, cudaMemcpyDeviceToDevice, 0);
    cudaMemcpyToSymbolAsync(ccol, pcol, C32 * sizeof(float),      0, cudaMemcpyDeviceToDevice, 0);
    cudaMemcpyToSymbolAsync(cg2,  g2,   C32 * sizeof(float),      0, cudaMemcpyDeviceToDevice, 0);
    cudaMemcpyToSymbolAsync(cbe2, be2,  C32 * sizeof(float),      0, cudaMemcpyDeviceToDevice, 0);

    int blocks = (nrows + 255) / 256;   // 256 rows per block (2 per thread)
    gnn_main_kernel<<<blocks, 128>>>(x, out, nrows);
}